// round 11
// baseline (speedup 1.0000x reference)
#include <cuda_runtime.h>
#include <cuda_fp16.h>
#include <stdint.h>

// Round 11: e-buffer in fp16 with a global 2^22 scale (p = e/S is scale-
// invariant). Halves the GEMM-epilogue write and the iter read: -16us of
// DRAM time. All else kept from the measured-good R10 structure.

// ---------------------------------------------------------------------------
#define QDIM   4096
#define NDIM   8192
#define DDIM   256
#define BM     128
#define BN     128
#define BK     64
#define NKT    4            // 256/64
#define STAGES 3
#define NITER  10
#define LOGSCALE 15.2492f   // 22 * ln(2): e' = exp(w + 22 ln2) = e * 2^22

// ---------------------------------------------------------------------------
// Device scratch (no allocation allowed)
// ---------------------------------------------------------------------------
__device__ __align__(128) __half g_A[(size_t)QDIM * DDIM];            // 2 MB
__device__ __align__(128) __half g_B[(size_t)NDIM * DDIM];            // 4 MB
__device__ __align__(128) float g_q2[QDIM];
__device__ __align__(128) float g_n2[NDIM];
__device__ __align__(128) __half g_e[(size_t)QDIM * NDIM];            // 64 MB (e * 2^22, fp16)

// ---------------------------------------------------------------------------
// PTX helpers (sm_80-era features only — final target is plain sm_100)
// ---------------------------------------------------------------------------
__device__ __forceinline__ uint32_t smem_to_u32(const void* p) {
    uint32_t a;
    asm("{ .reg .u64 t; cvta.to.shared.u64 t, %1; cvt.u32.u64 %0, t; }"
        : "=r"(a) : "l"(p));
    return a;
}

__device__ __forceinline__ void cpasync16(uint32_t dst, const void* src) {
    asm volatile("cp.async.cg.shared.global [%0], [%1], 16;"
                 :: "r"(dst), "l"(src) : "memory");
}
__device__ __forceinline__ void cp_commit() {
    asm volatile("cp.async.commit_group;" ::: "memory");
}
template <int N> __device__ __forceinline__ void cp_wait() {
    asm volatile("cp.async.wait_group %0;" :: "n"(N) : "memory");
}

__device__ __forceinline__ void ldmatrix_x4(uint32_t* r, uint32_t addr) {
    asm volatile("ldmatrix.sync.aligned.m8n8.x4.shared.b16 {%0,%1,%2,%3}, [%4];"
                 : "=r"(r[0]), "=r"(r[1]), "=r"(r[2]), "=r"(r[3]) : "r"(addr));
}

__device__ __forceinline__ void mma_fp16(float* c, const uint32_t* a,
                                         const uint32_t* b) {
    asm volatile(
        "mma.sync.aligned.m16n8k16.row.col.f32.f16.f16.f32 "
        "{%0,%1,%2,%3}, {%4,%5,%6,%7}, {%8,%9}, {%0,%1,%2,%3};"
        : "+f"(c[0]), "+f"(c[1]), "+f"(c[2]), "+f"(c[3])
        : "r"(a[0]), "r"(a[1]), "r"(a[2]), "r"(a[3]), "r"(b[0]), "r"(b[1]));
}

__device__ __forceinline__ void stcs32(void* p, uint32_t v) {
    asm volatile("st.global.cs.u32 [%0], %1;" :: "l"(p), "r"(v) : "memory");
}

// ---------------------------------------------------------------------------
// Kernel 1: fp32 row norms + fp16 convert. One warp per row.
// ---------------------------------------------------------------------------
__global__ void __launch_bounds__(256)
prep_kernel(const float* __restrict__ query, const float* __restrict__ neigh) {
    int warp = (blockIdx.x * 256 + threadIdx.x) >> 5;   // 0..12287
    int l = threadIdx.x & 31;
    bool isQ = warp < QDIM;
    int r = isQ ? warp : warp - QDIM;
    const float4* src = (const float4*)(isQ ? query + (size_t)r * DDIM
                                            : neigh + (size_t)r * DDIM);
    __half* dst = isQ ? g_A + (size_t)r * DDIM : g_B + (size_t)r * DDIM;

    float4 v0 = src[l * 2];
    float4 v1 = src[l * 2 + 1];

    float s = v0.x * v0.x + v0.y * v0.y + v0.z * v0.z + v0.w * v0.w
            + v1.x * v1.x + v1.y * v1.y + v1.z * v1.z + v1.w * v1.w;

    __half2 h0 = __floats2half2_rn(v0.x, v0.y);
    __half2 h1 = __floats2half2_rn(v0.z, v0.w);
    __half2 h2 = __floats2half2_rn(v1.x, v1.y);
    __half2 h3 = __floats2half2_rn(v1.z, v1.w);
    uint4 pk;
    pk.x = *(uint32_t*)&h0; pk.y = *(uint32_t*)&h1;
    pk.z = *(uint32_t*)&h2; pk.w = *(uint32_t*)&h3;
    ((uint4*)dst)[l] = pk;

#pragma unroll
    for (int off = 16; off > 0; off >>= 1)
        s += __shfl_xor_sync(0xffffffffu, s, off);
    if (l == 0) {
        if (isQ) g_q2[r] = s; else g_n2[r] = s;
    }
}

// ---------------------------------------------------------------------------
// Kernel 2: HMMA fp16 GEMM (128x128 tile, K=256) + fused epilogue:
// e' = exp(gumbel - dist + 22 ln2) stored as fp16. 8 warps 4(M)x2(N); 2 CTAs/SM
// ---------------------------------------------------------------------------
#define A_BYTES (BM * 128)                         // 16 KB
#define B_BYTES (BN * 128)                         // 16 KB
#define STAGE_BYTES (A_BYTES + B_BYTES)            // 32 KB
#define SMEM_DYN (STAGES * STAGE_BYTES)            // 96 KB

__device__ __forceinline__ void load_tile(uint32_t abuf, uint32_t bbuf,
                                          int kt, int qbase, int nbase,
                                          int tid) {
    const char* gA = (const char*)g_A + ((size_t)qbase * DDIM + (size_t)kt * BK) * 2;
    const char* gB = (const char*)g_B + ((size_t)nbase * DDIM + (size_t)kt * BK) * 2;
#pragma unroll
    for (int i = 0; i < 4; ++i) {
        int g = tid * 4 + i;
        int r = g >> 3, ku = g & 7;
        uint32_t so = (uint32_t)(r * 128 + ((ku ^ (r & 7)) << 4));
        cpasync16(abuf + so, gA + (size_t)r * (DDIM * 2) + (size_t)ku * 16);
        cpasync16(bbuf + so, gB + (size_t)r * (DDIM * 2) + (size_t)ku * 16);
    }
}

__global__ void __launch_bounds__(256, 2)
gemm_kernel(const float* __restrict__ gumbel) {
    extern __shared__ char smem_raw[];
    uint32_t sbase = smem_to_u32(smem_raw);

    int tid = threadIdx.x;
    int wid = tid >> 5;
    int l   = tid & 31;
    int warpm = wid & 3;          // 0..3 -> 32-row slab
    int warpn = wid >> 2;         // 0..1 -> 64-col slab

    int nbase = blockIdx.x * BN;
    int qbase = blockIdx.y * BM;

    uint32_t abuf[STAGES], bbuf[STAGES];
#pragma unroll
    for (int s = 0; s < STAGES; ++s) {
        abuf[s] = sbase + s * STAGE_BYTES;
        bbuf[s] = abuf[s] + A_BYTES;
    }

    load_tile(abuf[0], bbuf[0], 0, qbase, nbase, tid);
    cp_commit();
    load_tile(abuf[1], bbuf[1], 1, qbase, nbase, tid);
    cp_commit();

    float acc[2][8][4];
#pragma unroll
    for (int mt = 0; mt < 2; ++mt)
#pragma unroll
        for (int nt = 0; nt < 8; ++nt)
#pragma unroll
            for (int i = 0; i < 4; ++i) acc[mt][nt][i] = 0.f;

    int a_lr = (l & 15);
    int a_ku = (l >> 4);
    int b_lr = ((l >> 4) << 3) + (l & 7);
    int b_ku = ((l >> 3) & 1);

#pragma unroll
    for (int kt = 0; kt < NKT; ++kt) {
        const int s = kt % STAGES;
        if (kt < NKT - 1) cp_wait<1>();
        else              cp_wait<0>();
        __syncthreads();
        if (kt + 2 < NKT) {
            load_tile(abuf[(kt + 2) % STAGES], bbuf[(kt + 2) % STAGES],
                      kt + 2, qbase, nbase, tid);
            cp_commit();
        }

        uint32_t aS = abuf[s], bS = bbuf[s];
#pragma unroll
        for (int ks = 0; ks < 4; ++ks) {
            int kb = ks * 2;
            uint32_t afr[2][4];
#pragma unroll
            for (int mt = 0; mt < 2; ++mt) {
                int r = warpm * 32 + mt * 16 + a_lr;
                uint32_t addr = aS + r * 128 + (((kb + a_ku) ^ (r & 7)) << 4);
                ldmatrix_x4(afr[mt], addr);
            }
            uint32_t bfr[4][4];
#pragma unroll
            for (int bt = 0; bt < 4; ++bt) {
                int r = warpn * 64 + bt * 16 + b_lr;
                uint32_t addr = bS + r * 128 + (((kb + b_ku) ^ (r & 7)) << 4);
                ldmatrix_x4(bfr[bt], addr);
            }
#pragma unroll
            for (int mt = 0; mt < 2; ++mt)
#pragma unroll
                for (int nt = 0; nt < 8; ++nt)
                    mma_fp16(acc[mt][nt], afr[mt], &bfr[nt >> 1][(nt & 1) * 2]);
        }
    }

    // Fused epilogue: e' = exp(gumbel - sqrt(max(q2+n2-2dot,0)) + 22ln2) as fp16
    {
        int row0 = qbase + warpm * 32 + (l >> 2);
        int colb = nbase + warpn * 64 + (l & 3) * 2;
#pragma unroll
        for (int mt = 0; mt < 2; ++mt) {
            int rA = row0 + mt * 16;
            int rB = rA + 8;
            float q2a = __ldg(&g_q2[rA]) + LOGSCALE;   // fold scale into q2
            float q2b = __ldg(&g_q2[rB]) + LOGSCALE;   // (added after sqrt below)
            const float2* gAraw = (const float2*)(gumbel + (size_t)rA * NDIM);
            const float2* gBraw = (const float2*)(gumbel + (size_t)rB * NDIM);
            __half* eA = g_e + (size_t)rA * NDIM;
            __half* eB = g_e + (size_t)rB * NDIM;
            float q2a0 = q2a - LOGSCALE, q2b0 = q2b - LOGSCALE;
#pragma unroll
            for (int nt = 0; nt < 8; ++nt) {
                int col = colb + nt * 8;
                float n2a = __ldg(&g_n2[col]);
                float n2b = __ldg(&g_n2[col + 1]);
                float2 ga = __ldcs(&gAraw[col >> 1]);
                float2 gb = __ldcs(&gBraw[col >> 1]);
                float ax = __expf(ga.x + LOGSCALE - sqrtf(fmaxf(fmaf(-2.f, acc[mt][nt][0], q2a0 + n2a), 0.f)));
                float ay = __expf(ga.y + LOGSCALE - sqrtf(fmaxf(fmaf(-2.f, acc[mt][nt][1], q2a0 + n2b), 0.f)));
                float bx = __expf(gb.x + LOGSCALE - sqrtf(fmaxf(fmaf(-2.f, acc[mt][nt][2], q2b0 + n2a), 0.f)));
                float by = __expf(gb.y + LOGSCALE - sqrtf(fmaxf(fmaf(-2.f, acc[mt][nt][3], q2b0 + n2b), 0.f)));
                __half2 ha = __floats2half2_rn(ax, ay);
                __half2 hb = __floats2half2_rn(bx, by);
                stcs32(eA + col, *(uint32_t*)&ha);
                stcs32(eB + col, *(uint32_t*)&hb);
            }
        }
    }
}

// ---------------------------------------------------------------------------
// Kernel 3: iterative relaxed top-k; one block (256 thr) per query row,
// 32 elems/thread. Input is fp16 e' (global scale cancels in p = e/S).
// 10x { S = sum(e); p = e/S; khot += p; e = fma(-p, e, e) }
// ---------------------------------------------------------------------------
__global__ void __launch_bounds__(256)
iter_kernel(float* __restrict__ out) {
    __shared__ float sred[2][8];

    int t = threadIdx.x;
    int w = t >> 5, l = t & 31;
    const uint4* erow = (const uint4*)(g_e + (size_t)blockIdx.x * NDIM);
    float4* orow = (float4*)(out + (size_t)blockIdx.x * NDIM);

    float e[32], kh[32];
#pragma unroll
    for (int i = 0; i < 4; ++i) {          // 4 x 16B = 32 halves
        uint4 v = __ldcs(&erow[i * 256 + t]);
        uint32_t u[4] = {v.x, v.y, v.z, v.w};
#pragma unroll
        for (int j = 0; j < 4; ++j) {
            float2 f = __half22float2(*(__half2*)&u[j]);
            e[i * 8 + j * 2 + 0] = f.x;
            e[i * 8 + j * 2 + 1] = f.y;
        }
    }
#pragma unroll
    for (int j = 0; j < 32; ++j) kh[j] = 0.f;

#pragma unroll
    for (int it = 0; it < NITER; ++it) {
        int buf = it & 1;
        float s4[4] = {0.f, 0.f, 0.f, 0.f};
#pragma unroll
        for (int j = 0; j < 32; j += 4) {
            s4[0] += e[j]; s4[1] += e[j + 1]; s4[2] += e[j + 2]; s4[3] += e[j + 3];
        }
        float s = (s4[0] + s4[1]) + (s4[2] + s4[3]);
#pragma unroll
        for (int o = 16; o > 0; o >>= 1)
            s += __shfl_xor_sync(0xffffffffu, s, o);
        if (l == 0) sred[buf][w] = s;
        __syncthreads();
        float tot = sred[buf][0];
#pragma unroll
        for (int j = 1; j < 8; ++j) tot += sred[buf][j];
        float inv = __fdividef(1.0f, tot);
#pragma unroll
        for (int j = 0; j < 32; ++j) {
            float p = e[j] * inv;
            kh[j] += p;
            e[j] = fmaf(-p, e[j], e[j]);   // e *= (1 - p)
        }
    }

    // output layout must match load layout: thread t holds elems
    // [i*2048 + t*8 .. +8) for i in 0..3  (uint4 = 8 halves)
#pragma unroll
    for (int i = 0; i < 4; ++i) {
        float4 o0, o1;
        o0.x = kh[i * 8 + 0]; o0.y = kh[i * 8 + 1];
        o0.z = kh[i * 8 + 2]; o0.w = kh[i * 8 + 3];
        o1.x = kh[i * 8 + 4]; o1.y = kh[i * 8 + 5];
        o1.z = kh[i * 8 + 6]; o1.w = kh[i * 8 + 7];
        __stcs(&orow[i * 512 + t * 2 + 0], o0);
        __stcs(&orow[i * 512 + t * 2 + 1], o1);
    }
}

// ---------------------------------------------------------------------------
// Launch (serial; overlap impossible: GEMM occupies the full register file)
// ---------------------------------------------------------------------------
extern "C" void kernel_launch(void* const* d_in, const int* in_sizes, int n_in,
                              void* d_out, int out_size) {
    const float* query  = (const float*)d_in[0];   // [4096, 256]
    const float* neigh  = (const float*)d_in[1];   // [1, 8192, 256]
    const float* gumbel = (const float*)d_in[2];   // [4096, 8192]
    float* out = (float*)d_out;                    // [4096, 8192]

    prep_kernel<<<(QDIM + NDIM) / 8, 256>>>(query, neigh);

    cudaFuncSetAttribute(gemm_kernel,
                         cudaFuncAttributeMaxDynamicSharedMemorySize, SMEM_DYN);
    dim3 grid(NDIM / BN, QDIM / BM);
    gemm_kernel<<<grid, 256, SMEM_DYN>>>(gumbel);

    iter_kernel<<<QDIM, 256>>>(out);
}

// round 12
// speedup vs baseline: 1.1204x; 1.1204x over previous
#include <cuda_runtime.h>
#include <cuda_fp16.h>
#include <stdint.h>

// Round 12: revert e-buffer to fp32 (fp16 regressed: no time win, worse err).
// New: iter kernel uses packed f32x2 math (SASS FFMA2, PTX-only) to halve its
// FMA-pipe time, which R11 showed to be the co-limiter with DRAM.

// ---------------------------------------------------------------------------
#define QDIM   4096
#define NDIM   8192
#define DDIM   256
#define BM     128
#define BN     128
#define BK     64
#define NKT    4            // 256/64
#define STAGES 3
#define NITER  10

typedef unsigned long long u64;

// ---------------------------------------------------------------------------
// Device scratch (no allocation allowed)
// ---------------------------------------------------------------------------
__device__ __align__(128) __half g_A[(size_t)QDIM * DDIM];            // 2 MB
__device__ __align__(128) __half g_B[(size_t)NDIM * DDIM];            // 4 MB
__device__ __align__(128) float g_q2[QDIM];
__device__ __align__(128) float g_n2[NDIM];
__device__ __align__(128) float g_w[(size_t)QDIM * NDIM];             // 128 MB (stores e=exp(w))

// ---------------------------------------------------------------------------
// PTX helpers
// ---------------------------------------------------------------------------
__device__ __forceinline__ uint32_t smem_to_u32(const void* p) {
    uint32_t a;
    asm("{ .reg .u64 t; cvta.to.shared.u64 t, %1; cvt.u32.u64 %0, t; }"
        : "=r"(a) : "l"(p));
    return a;
}

__device__ __forceinline__ void cpasync16(uint32_t dst, const void* src) {
    asm volatile("cp.async.cg.shared.global [%0], [%1], 16;"
                 :: "r"(dst), "l"(src) : "memory");
}
__device__ __forceinline__ void cp_commit() {
    asm volatile("cp.async.commit_group;" ::: "memory");
}
template <int N> __device__ __forceinline__ void cp_wait() {
    asm volatile("cp.async.wait_group %0;" :: "n"(N) : "memory");
}

__device__ __forceinline__ void ldmatrix_x4(uint32_t* r, uint32_t addr) {
    asm volatile("ldmatrix.sync.aligned.m8n8.x4.shared.b16 {%0,%1,%2,%3}, [%4];"
                 : "=r"(r[0]), "=r"(r[1]), "=r"(r[2]), "=r"(r[3]) : "r"(addr));
}

__device__ __forceinline__ void mma_fp16(float* c, const uint32_t* a,
                                         const uint32_t* b) {
    asm volatile(
        "mma.sync.aligned.m16n8k16.row.col.f32.f16.f16.f32 "
        "{%0,%1,%2,%3}, {%4,%5,%6,%7}, {%8,%9}, {%0,%1,%2,%3};"
        : "+f"(c[0]), "+f"(c[1]), "+f"(c[2]), "+f"(c[3])
        : "r"(a[0]), "r"(a[1]), "r"(a[2]), "r"(a[3]), "r"(b[0]), "r"(b[1]));
}

// ---- packed f32x2 (FFMA2 path; PTX-only, sm_100-family) ----
__device__ __forceinline__ u64 pack2(float lo, float hi) {
    u64 r; asm("mov.b64 %0, {%1, %2};" : "=l"(r) : "f"(lo), "f"(hi)); return r;
}
__device__ __forceinline__ void unpack2(float& lo, float& hi, u64 v) {
    asm("mov.b64 {%0, %1}, %2;" : "=f"(lo), "=f"(hi) : "l"(v));
}
__device__ __forceinline__ u64 mul2(u64 a, u64 b) {
    u64 r; asm("mul.rn.f32x2 %0, %1, %2;" : "=l"(r) : "l"(a), "l"(b)); return r;
}
__device__ __forceinline__ u64 add2(u64 a, u64 b) {
    u64 r; asm("add.rn.f32x2 %0, %1, %2;" : "=l"(r) : "l"(a), "l"(b)); return r;
}
__device__ __forceinline__ u64 fma2(u64 a, u64 b, u64 c) {
    u64 r; asm("fma.rn.f32x2 %0, %1, %2, %3;" : "=l"(r) : "l"(a), "l"(b), "l"(c)); return r;
}

// ---------------------------------------------------------------------------
// Kernel 1: fp32 row norms + fp16 convert. One warp per row.
// ---------------------------------------------------------------------------
__global__ void __launch_bounds__(256)
prep_kernel(const float* __restrict__ query, const float* __restrict__ neigh) {
    int warp = (blockIdx.x * 256 + threadIdx.x) >> 5;   // 0..12287
    int l = threadIdx.x & 31;
    bool isQ = warp < QDIM;
    int r = isQ ? warp : warp - QDIM;
    const float4* src = (const float4*)(isQ ? query + (size_t)r * DDIM
                                            : neigh + (size_t)r * DDIM);
    __half* dst = isQ ? g_A + (size_t)r * DDIM : g_B + (size_t)r * DDIM;

    float4 v0 = src[l * 2];
    float4 v1 = src[l * 2 + 1];

    float s = v0.x * v0.x + v0.y * v0.y + v0.z * v0.z + v0.w * v0.w
            + v1.x * v1.x + v1.y * v1.y + v1.z * v1.z + v1.w * v1.w;

    __half2 h0 = __floats2half2_rn(v0.x, v0.y);
    __half2 h1 = __floats2half2_rn(v0.z, v0.w);
    __half2 h2 = __floats2half2_rn(v1.x, v1.y);
    __half2 h3 = __floats2half2_rn(v1.z, v1.w);
    uint4 pk;
    pk.x = *(uint32_t*)&h0; pk.y = *(uint32_t*)&h1;
    pk.z = *(uint32_t*)&h2; pk.w = *(uint32_t*)&h3;
    ((uint4*)dst)[l] = pk;

#pragma unroll
    for (int off = 16; off > 0; off >>= 1)
        s += __shfl_xor_sync(0xffffffffu, s, off);
    if (l == 0) {
        if (isQ) g_q2[r] = s; else g_n2[r] = s;
    }
}

// ---------------------------------------------------------------------------
// Kernel 2: HMMA fp16 GEMM (128x128 tile, K=256) + fused epilogue -> g_w
// stores e = exp(gumbel - dist). 8 warps 4(M)x2(N); 2 CTAs/SM  (R10 verbatim)
// ---------------------------------------------------------------------------
#define A_BYTES (BM * 128)                         // 16 KB
#define B_BYTES (BN * 128)                         // 16 KB
#define STAGE_BYTES (A_BYTES + B_BYTES)            // 32 KB
#define SMEM_DYN (STAGES * STAGE_BYTES)            // 96 KB

__device__ __forceinline__ void load_tile(uint32_t abuf, uint32_t bbuf,
                                          int kt, int qbase, int nbase,
                                          int tid) {
    const char* gA = (const char*)g_A + ((size_t)qbase * DDIM + (size_t)kt * BK) * 2;
    const char* gB = (const char*)g_B + ((size_t)nbase * DDIM + (size_t)kt * BK) * 2;
#pragma unroll
    for (int i = 0; i < 4; ++i) {
        int g = tid * 4 + i;
        int r = g >> 3, ku = g & 7;
        uint32_t so = (uint32_t)(r * 128 + ((ku ^ (r & 7)) << 4));
        cpasync16(abuf + so, gA + (size_t)r * (DDIM * 2) + (size_t)ku * 16);
        cpasync16(bbuf + so, gB + (size_t)r * (DDIM * 2) + (size_t)ku * 16);
    }
}

__global__ void __launch_bounds__(256, 2)
gemm_kernel(const float* __restrict__ gumbel) {
    extern __shared__ char smem_raw[];
    uint32_t sbase = smem_to_u32(smem_raw);

    int tid = threadIdx.x;
    int wid = tid >> 5;
    int l   = tid & 31;
    int warpm = wid & 3;          // 0..3 -> 32-row slab
    int warpn = wid >> 2;         // 0..1 -> 64-col slab

    int nbase = blockIdx.x * BN;
    int qbase = blockIdx.y * BM;

    uint32_t abuf[STAGES], bbuf[STAGES];
#pragma unroll
    for (int s = 0; s < STAGES; ++s) {
        abuf[s] = sbase + s * STAGE_BYTES;
        bbuf[s] = abuf[s] + A_BYTES;
    }

    load_tile(abuf[0], bbuf[0], 0, qbase, nbase, tid);
    cp_commit();
    load_tile(abuf[1], bbuf[1], 1, qbase, nbase, tid);
    cp_commit();

    float acc[2][8][4];
#pragma unroll
    for (int mt = 0; mt < 2; ++mt)
#pragma unroll
        for (int nt = 0; nt < 8; ++nt)
#pragma unroll
            for (int i = 0; i < 4; ++i) acc[mt][nt][i] = 0.f;

    int a_lr = (l & 15);
    int a_ku = (l >> 4);
    int b_lr = ((l >> 4) << 3) + (l & 7);
    int b_ku = ((l >> 3) & 1);

#pragma unroll
    for (int kt = 0; kt < NKT; ++kt) {
        const int s = kt % STAGES;
        if (kt < NKT - 1) cp_wait<1>();
        else              cp_wait<0>();
        __syncthreads();
        if (kt + 2 < NKT) {
            load_tile(abuf[(kt + 2) % STAGES], bbuf[(kt + 2) % STAGES],
                      kt + 2, qbase, nbase, tid);
            cp_commit();
        }

        uint32_t aS = abuf[s], bS = bbuf[s];
#pragma unroll
        for (int ks = 0; ks < 4; ++ks) {
            int kb = ks * 2;
            uint32_t afr[2][4];
#pragma unroll
            for (int mt = 0; mt < 2; ++mt) {
                int r = warpm * 32 + mt * 16 + a_lr;
                uint32_t addr = aS + r * 128 + (((kb + a_ku) ^ (r & 7)) << 4);
                ldmatrix_x4(afr[mt], addr);
            }
            uint32_t bfr[4][4];
#pragma unroll
            for (int bt = 0; bt < 4; ++bt) {
                int r = warpn * 64 + bt * 16 + b_lr;
                uint32_t addr = bS + r * 128 + (((kb + b_ku) ^ (r & 7)) << 4);
                ldmatrix_x4(bfr[bt], addr);
            }
#pragma unroll
            for (int mt = 0; mt < 2; ++mt)
#pragma unroll
                for (int nt = 0; nt < 8; ++nt)
                    mma_fp16(acc[mt][nt], afr[mt], &bfr[nt >> 1][(nt & 1) * 2]);
        }
    }

    // Fused epilogue: e = exp(gumbel - sqrt(max(q2 + n2 - 2*dot, 0)))
    {
        int row0 = qbase + warpm * 32 + (l >> 2);
        int colb = nbase + warpn * 64 + (l & 3) * 2;
#pragma unroll
        for (int mt = 0; mt < 2; ++mt) {
            int rA = row0 + mt * 16;
            int rB = rA + 8;
            float q2a = __ldg(&g_q2[rA]);
            float q2b = __ldg(&g_q2[rB]);
            const float2* gAraw = (const float2*)(gumbel + (size_t)rA * NDIM);
            const float2* gBraw = (const float2*)(gumbel + (size_t)rB * NDIM);
            float2* wA = (float2*)(g_w + (size_t)rA * NDIM);
            float2* wB = (float2*)(g_w + (size_t)rB * NDIM);
#pragma unroll
            for (int nt = 0; nt < 8; ++nt) {
                int col = colb + nt * 8;
                float n2a = __ldg(&g_n2[col]);
                float n2b = __ldg(&g_n2[col + 1]);
                float2 ga = __ldcs(&gAraw[col >> 1]);
                float2 gb = __ldcs(&gBraw[col >> 1]);
                float2 oa, ob;
                oa.x = __expf(ga.x - sqrtf(fmaxf(fmaf(-2.f, acc[mt][nt][0], q2a + n2a), 0.f)));
                oa.y = __expf(ga.y - sqrtf(fmaxf(fmaf(-2.f, acc[mt][nt][1], q2a + n2b), 0.f)));
                ob.x = __expf(gb.x - sqrtf(fmaxf(fmaf(-2.f, acc[mt][nt][2], q2b + n2a), 0.f)));
                ob.y = __expf(gb.y - sqrtf(fmaxf(fmaf(-2.f, acc[mt][nt][3], q2b + n2b), 0.f)));
                __stcs(&wA[col >> 1], oa);
                __stcs(&wB[col >> 1], ob);
            }
        }
    }
}

// ---------------------------------------------------------------------------
// Kernel 3: iterative relaxed top-k; one block (256 thr) per query row,
// 32 elems/thread, packed f32x2 math.
// 10x { S = sum(e); np = -e/S; kh -= np; e = fma(np, e, e) }
// ---------------------------------------------------------------------------
__global__ void __launch_bounds__(256)
iter_kernel(float* __restrict__ out) {
    __shared__ float sred[2][8];

    int t = threadIdx.x;
    int w = t >> 5, l = t & 31;
    const float4* erow = (const float4*)(g_w + (size_t)blockIdx.x * NDIM);
    float4* orow = (float4*)(out + (size_t)blockIdx.x * NDIM);

    u64 e2[16], kh2[16];
#pragma unroll
    for (int i = 0; i < 8; ++i) {
        float4 v = __ldcs(&erow[i * 256 + t]);
        e2[i * 2 + 0] = pack2(v.x, v.y);
        e2[i * 2 + 1] = pack2(v.z, v.w);
    }
    const u64 zero2 = pack2(0.f, 0.f);
    const u64 none2 = pack2(-1.f, -1.f);
#pragma unroll
    for (int j = 0; j < 16; ++j) kh2[j] = zero2;

#pragma unroll
    for (int it = 0; it < NITER; ++it) {
        int buf = it & 1;
        u64 sa = e2[0], sb = e2[1], sc = e2[2], sd = e2[3];
#pragma unroll
        for (int j = 4; j < 16; j += 4) {
            sa = add2(sa, e2[j]);     sb = add2(sb, e2[j + 1]);
            sc = add2(sc, e2[j + 2]); sd = add2(sd, e2[j + 3]);
        }
        u64 st2 = add2(add2(sa, sb), add2(sc, sd));
        float slo, shi; unpack2(slo, shi, st2);
        float s = slo + shi;
#pragma unroll
        for (int o = 16; o > 0; o >>= 1)
            s += __shfl_xor_sync(0xffffffffu, s, o);
        if (l == 0) sred[buf][w] = s;
        __syncthreads();
        float tot = sred[buf][0];
#pragma unroll
        for (int j = 1; j < 8; ++j) tot += sred[buf][j];
        float ninv = -__fdividef(1.0f, tot);
        u64 ninv2 = pack2(ninv, ninv);
#pragma unroll
        for (int j = 0; j < 16; ++j) {
            u64 np = mul2(e2[j], ninv2);        // np = -p
            kh2[j] = fma2(np, none2, kh2[j]);   // kh += p
            e2[j]  = fma2(np, e2[j], e2[j]);    // e *= (1 - p)
        }
    }

#pragma unroll
    for (int i = 0; i < 8; ++i) {
        float4 o4;
        unpack2(o4.x, o4.y, kh2[i * 2 + 0]);
        unpack2(o4.z, o4.w, kh2[i * 2 + 1]);
        __stcs(&orow[i * 256 + t], o4);
    }
}

// ---------------------------------------------------------------------------
// Launch (serial; overlap impossible: GEMM occupies the full register file)
// ---------------------------------------------------------------------------
extern "C" void kernel_launch(void* const* d_in, const int* in_sizes, int n_in,
                              void* d_out, int out_size) {
    const float* query  = (const float*)d_in[0];   // [4096, 256]
    const float* neigh  = (const float*)d_in[1];   // [1, 8192, 256]
    const float* gumbel = (const float*)d_in[2];   // [4096, 8192]
    float* out = (float*)d_out;                    // [4096, 8192]

    prep_kernel<<<(QDIM + NDIM) / 8, 256>>>(query, neigh);

    cudaFuncSetAttribute(gemm_kernel,
                         cudaFuncAttributeMaxDynamicSharedMemorySize, SMEM_DYN);
    dim3 grid(NDIM / BN, QDIM / BM);
    gemm_kernel<<<grid, 256, SMEM_DYN>>>(gumbel);

    iter_kernel<<<QDIM, 256>>>(out);
}